// round 3
// baseline (speedup 1.0000x reference)
#include <cuda_runtime.h>

#define BB 4
#define CIN 64
#define CO 128
#define HH 256
#define WW 256
#define HWP 65536
#define NOUT (BB*4*HWP)   // 1048576

typedef unsigned long long u64;

// scratch: h = conv1(x)  [B, 128, 256, 256] fp32 = 128 MB
__device__ float g_h[(size_t)BB * CO * HWP];
// pre-transposed conv1 weights: [rk = ci*9+k][cout]  (576 x 128)
__device__ float g_Wt[576 * 128];

// ---- f32x2 helpers (packed 2xfp32 FMA — sm_103a FFMA2 path) -------------
__device__ __forceinline__ void fma2(u64& d, u64 a, u64 b) {
    asm("fma.rn.f32x2 %0, %1, %2, %0;" : "+l"(d) : "l"(a), "l"(b));
}
__device__ __forceinline__ u64 dup2(float x) {
    u64 d; asm("mov.b64 %0, {%1, %1};" : "=l"(d) : "f"(x)); return d;
}
__device__ __forceinline__ float2 unpk(u64 d) {
    float2 r; asm("mov.b64 {%0, %1}, %2;" : "=f"(r.x), "=f"(r.y) : "l"(d));
    return r;
}

// ---------------------------------------------------------------------------
// Kernel 0: transpose conv1 weights -> [rk][cout]
// ---------------------------------------------------------------------------
__global__ void transpose_w(const float* __restrict__ Wc) {
    int i = blockIdx.x * 256 + threadIdx.x;   // < 576*128
    int cout = i & 127, rk = i >> 7;
    g_Wt[rk * 128 + cout] = Wc[cout * 576 + rk];
}

// ---------------------------------------------------------------------------
// Kernel 1: 3x3 conv, 64 -> 128, pad 1, + bias. (unchanged from R2 — near
// FFMA2 pipe ceiling)
// ---------------------------------------------------------------------------
__global__ __launch_bounds__(256, 2) void conv1_kernel(
    const float* __restrict__ x, const float* __restrict__ bc)
{
    __shared__ float sW[72 * 128];   // [rk][cout]
    __shared__ float sX[8 * 6 * 36]; // [ci][row][col], stride 36

    const int b  = blockIdx.z;
    const int y0 = blockIdx.y * 4;
    const int x0 = blockIdx.x * 32;
    const int tid  = threadIdx.x;
    const int cg   = tid >> 5;
    const int q    = tid & 31;
    const int row  = q >> 3;
    const int colq = (q & 7) * 4;

    u64 acc[8][4];
#pragma unroll
    for (int p = 0; p < 8; p++)
#pragma unroll
        for (int j = 0; j < 4; j++) acc[p][j] = 0ull;

    for (int cc = 0; cc < 8; cc++) {
        __syncthreads();
#pragma unroll 4
        for (int i = tid; i < 72 * 128; i += 256)
            sW[i] = g_Wt[cc * (72 * 128) + i];
        for (int i = tid; i < 8 * 6 * 34; i += 256) {
            int ci = i / 204, r = (i / 34) % 6, c = i % 34;
            int gy = y0 - 1 + r, gx = x0 - 1 + c;
            float v = 0.f;
            if (gy >= 0 && gy < HH && gx >= 0 && gx < WW)
                v = x[(((size_t)b * CIN + cc * 8 + ci) * HH + gy) * WW + gx];
            sX[(ci * 6 + r) * 36 + c] = v;
        }
        __syncthreads();

#pragma unroll 2
        for (int ci = 0; ci < 8; ci++) {
#pragma unroll
            for (int ky = 0; ky < 3; ky++) {
                const float* xr = &sX[(ci * 6 + row + ky) * 36 + colq];
                float4 xa = *reinterpret_cast<const float4*>(xr);
                float4 xb = *reinterpret_cast<const float4*>(xr + 4);
                u64 xd[6];
                xd[0] = dup2(xa.x); xd[1] = dup2(xa.y);
                xd[2] = dup2(xa.z); xd[3] = dup2(xa.w);
                xd[4] = dup2(xb.x); xd[5] = dup2(xb.y);
#pragma unroll
                for (int kx = 0; kx < 3; kx++) {
                    const ulonglong2* wp = reinterpret_cast<const ulonglong2*>(
                        &sW[(ci * 9 + ky * 3 + kx) * 128 + cg * 16]);
                    ulonglong2 wA = wp[0];
                    ulonglong2 wB = wp[1];
                    ulonglong2 wC = wp[2];
                    ulonglong2 wD = wp[3];
#pragma unroll
                    for (int j = 0; j < 4; j++) {
                        u64 xv = xd[kx + j];
                        fma2(acc[0][j], wA.x, xv);
                        fma2(acc[1][j], wA.y, xv);
                        fma2(acc[2][j], wB.x, xv);
                        fma2(acc[3][j], wB.y, xv);
                        fma2(acc[4][j], wC.x, xv);
                        fma2(acc[5][j], wC.y, xv);
                        fma2(acc[6][j], wD.x, xv);
                        fma2(acc[7][j], wD.y, xv);
                    }
                }
            }
        }
    }

#pragma unroll
    for (int p = 0; p < 8; p++) {
        int c0 = cg * 16 + 2 * p;
        float b0 = bc[c0], b1 = bc[c0 + 1];
        float4 v0, v1;
        float2 f;
        f = unpk(acc[p][0]); v0.x = f.x + b0; v1.x = f.y + b1;
        f = unpk(acc[p][1]); v0.y = f.x + b0; v1.y = f.y + b1;
        f = unpk(acc[p][2]); v0.z = f.x + b0; v1.z = f.y + b1;
        f = unpk(acc[p][3]); v0.w = f.x + b0; v1.w = f.y + b1;
        size_t base = (((size_t)b * CO + c0) * HH + y0 + row) * WW + x0 + colq;
        *reinterpret_cast<float4*>(&g_h[base]) = v0;
        *reinterpret_cast<float4*>(&g_h[base + (size_t)HH * WW]) = v1;
    }
}

// ---------------------------------------------------------------------------
// Kernel 2 (FUSED): MC dropout mean/var + AU conv, single pass over h.
// Block: 256 threads = 8 rows x 32 cols pixel tile, 1 pixel/thread.
// Streams h in 32 chunks of 4 channels via haloed smem tile (10 x 34).
// ---------------------------------------------------------------------------
#define FILL_N 1360          // 4 ci * 10 rows * 34 cols
#define FILL_SLOTS 6

__global__ __launch_bounds__(256, 2) void mcau_kernel(
    const float* __restrict__ lms, const float* __restrict__ Wo,
    const float* __restrict__ bo, const float* __restrict__ masks,
    const float* __restrict__ Wa, const float* __restrict__ ba,
    float* __restrict__ out)
{
    __shared__ float sWm[128 * 64];     // [c][t][o], o fastest (32 KB)
    __shared__ float sWa[128 * 9 * 4];  // [(ci*9+k)*4 + o] (18 KB)
    __shared__ float sX[4 * 10 * 36];   // 4 ci x 10 rows x 34 cols, stride 36

    const int tid = threadIdx.x;
    for (int i = tid; i < 128 * 64; i += 256) {
        int c = i >> 6, t = (i >> 2) & 15, o = i & 3;
        sWm[i] = Wo[o * 128 + c] * masks[t * 128 + c];
    }
    for (int i = tid; i < 128 * 36; i += 256) {
        int ci = i / 36, rem = i % 36, k = rem >> 2, o = rem & 3;
        sWa[i] = Wa[(o * 128 + ci) * 9 + k];
    }

    const int b  = blockIdx.z;
    const int y0 = blockIdx.y * 8;
    const int x0 = blockIdx.x * 32;
    const int row = tid >> 5;        // 0..7
    const int col = tid & 31;        // 0..31

    // ---- precompute fill slots (hoists ALL div/mod out of the main loop) ----
    int smoff[FILL_SLOTS];
    int goff[FILL_SLOTS];            // g_h index for ci-chunk base, -1 = OOB/unused
#pragma unroll
    for (int s = 0; s < FILL_SLOTS; s++) {
        int i = tid + s * 256;
        smoff[s] = -1; goff[s] = -1;
        if (i < FILL_N) {
            int ci = i / 340, r = (i / 34) % 10, c = i % 34;
            int gy = y0 - 1 + r, gx = x0 - 1 + c;
            smoff[s] = (ci * 10 + r) * 36 + c;
            if (gy >= 0 && gy < HH && gx >= 0 && gx < WW)
                goff[s] = ((b * CO + ci) * HH + gy) * WW + gx;
        }
    }

    u64 mcA[16], mcB[16];            // mc accumulators: (o0,o1) / (o2,o3) per t
#pragma unroll
    for (int t = 0; t < 16; t++) { mcA[t] = 0ull; mcB[t] = 0ull; }
    u64 auA = 0ull, auB = 0ull;      // au accumulators: (o0,o1) / (o2,o3)

    for (int cc = 0; cc < 32; cc++) {
        __syncthreads();
        const int cshift = cc * 4 * HWP;
#pragma unroll
        for (int s = 0; s < FILL_SLOTS; s++) {
            if (smoff[s] >= 0) {
                float v = (goff[s] >= 0) ? __ldg(&g_h[goff[s] + cshift]) : 0.f;
                sX[smoff[s]] = v;
            }
        }
        __syncthreads();

#pragma unroll
        for (int ci = 0; ci < 4; ci++) {
            // --- mc: interior point ---
            float hv = sX[(ci * 10 + row + 1) * 36 + col + 1];
            u64 hd = dup2(hv);
            const ulonglong2* wr =
                reinterpret_cast<const ulonglong2*>(&sWm[(cc * 4 + ci) * 64]);
#pragma unroll
            for (int t = 0; t < 16; t++) {
                ulonglong2 w = wr[t];       // broadcast LDS.128
                fma2(mcA[t], w.x, hd);
                fma2(mcB[t], w.y, hd);
            }
            // --- au: 3x3 neighborhood ---
#pragma unroll
            for (int ky = 0; ky < 3; ky++) {
                const float* xr = &sX[(ci * 10 + row + ky) * 36 + col];
                float v0 = xr[0], v1 = xr[1], v2 = xr[2];
                const ulonglong2* wk = reinterpret_cast<const ulonglong2*>(
                    &sWa[((cc * 4 + ci) * 9 + ky * 3) * 4]);
                ulonglong2 w0 = wk[0], w1 = wk[1], w2 = wk[2];
                u64 x0d = dup2(v0), x1d = dup2(v1), x2d = dup2(v2);
                fma2(auA, w0.x, x0d); fma2(auB, w0.y, x0d);
                fma2(auA, w1.x, x1d); fma2(auB, w1.y, x1d);
                fma2(auA, w2.x, x2d); fma2(auB, w2.y, x2d);
            }
        }
    }

    // ---- epilogue ----
    const int pix  = (y0 + row) * WW + x0 + col;

    // mc: tanh, mean, unbiased var
    float a[16][4];
#pragma unroll
    for (int t = 0; t < 16; t++) {
        float2 f01 = unpk(mcA[t]);
        float2 f23 = unpk(mcB[t]);
        a[t][0] = f01.x; a[t][1] = f01.y; a[t][2] = f23.x; a[t][3] = f23.y;
    }
#pragma unroll
    for (int o = 0; o < 4; o++) {
        float bb = bo[o];
        float s[16];
        float sum = 0.f;
#pragma unroll
        for (int t = 0; t < 16; t++) {
            float v = tanhf(a[t][o] + bb);
            s[t] = v;
            sum += v;
        }
        float mn = sum * 0.0625f;
        float var = 0.f;
#pragma unroll
        for (int t = 0; t < 16; t++) {
            float d = s[t] - mn;
            var += d * d;
        }
        var *= (1.f / 15.f);
        int oidx = (b * 4 + o) * HWP + pix;
        out[NOUT + oidx]     = var;              // EU
        out[2 * NOUT + oidx] = mn + lms[oidx];   // mean
    }

    // au: sigmoid
    {
        float2 f01 = unpk(auA);
        float2 f23 = unpk(auB);
        float av[4] = { f01.x, f01.y, f23.x, f23.y };
#pragma unroll
        for (int o = 0; o < 4; o++) {
            float v = 1.f / (1.f + expf(-(av[o] + ba[o])));
            out[(b * 4 + o) * HWP + pix] = v;    // AU
        }
    }
}

// ---------------------------------------------------------------------------
extern "C" void kernel_launch(void* const* d_in, const int* in_sizes, int n_in,
                              void* d_out, int out_size) {
    const float* x     = (const float*)d_in[0];
    const float* lms   = (const float*)d_in[1];
    const float* Wc    = (const float*)d_in[2];
    const float* bc    = (const float*)d_in[3];
    const float* Wo    = (const float*)d_in[4];
    const float* bo    = (const float*)d_in[5];
    const float* Wa    = (const float*)d_in[6];
    const float* ba    = (const float*)d_in[7];
    const float* masks = (const float*)d_in[8];
    float* out = (float*)d_out;

    transpose_w<<<288, 256>>>(Wc);
    conv1_kernel<<<dim3(8, 64, 4), 256>>>(x, bc);
    mcau_kernel<<<dim3(8, 32, 4), 256>>>(lms, Wo, bo, masks, Wa, ba, out);
}

// round 4
// speedup vs baseline: 1.0056x; 1.0056x over previous
#include <cuda_runtime.h>

#define BB 4
#define CIN 64
#define CO 128
#define HH 256
#define WW 256
#define HWP 65536
#define NOUT (BB*4*HWP)   // 1048576

typedef unsigned long long u64;

// scratch: h = conv1(x)  [B, 128, 256, 256] fp32 = 128 MB
__device__ float g_h[(size_t)BB * CO * HWP];
// pre-transposed conv1 weights: [rk = ci*9+k][cout]  (576 x 128)
__device__ float g_Wt[576 * 128];

// ---- f32x2 helpers (packed 2xfp32 FMA — sm_103a FFMA2 path) -------------
__device__ __forceinline__ void fma2(u64& d, u64 a, u64 b) {
    asm("fma.rn.f32x2 %0, %1, %2, %0;" : "+l"(d) : "l"(a), "l"(b));
}
__device__ __forceinline__ u64 dup2(float x) {
    u64 d; asm("mov.b64 %0, {%1, %1};" : "=l"(d) : "f"(x)); return d;
}
__device__ __forceinline__ float2 unpk(u64 d) {
    float2 r; asm("mov.b64 {%0, %1}, %2;" : "=f"(r.x), "=f"(r.y) : "l"(d));
    return r;
}

// ---------------------------------------------------------------------------
// Kernel 0: transpose conv1 weights -> [rk][cout]
// ---------------------------------------------------------------------------
__global__ void transpose_w(const float* __restrict__ Wc) {
    int i = blockIdx.x * 256 + threadIdx.x;   // < 576*128
    int cout = i & 127, rk = i >> 7;
    g_Wt[rk * 128 + cout] = Wc[cout * 576 + rk];
}

// ---------------------------------------------------------------------------
// Kernel 1: 3x3 conv, 64 -> 128, pad 1, + bias. (unchanged from R2 — near
// FFMA2 pipe ceiling)
// ---------------------------------------------------------------------------
__global__ __launch_bounds__(256, 2) void conv1_kernel(
    const float* __restrict__ x, const float* __restrict__ bc)
{
    __shared__ float sW[72 * 128];   // [rk][cout]
    __shared__ float sX[8 * 6 * 36]; // [ci][row][col], stride 36

    const int b  = blockIdx.z;
    const int y0 = blockIdx.y * 4;
    const int x0 = blockIdx.x * 32;
    const int tid  = threadIdx.x;
    const int cg   = tid >> 5;
    const int q    = tid & 31;
    const int row  = q >> 3;
    const int colq = (q & 7) * 4;

    u64 acc[8][4];
#pragma unroll
    for (int p = 0; p < 8; p++)
#pragma unroll
        for (int j = 0; j < 4; j++) acc[p][j] = 0ull;

    for (int cc = 0; cc < 8; cc++) {
        __syncthreads();
#pragma unroll 4
        for (int i = tid; i < 72 * 128; i += 256)
            sW[i] = g_Wt[cc * (72 * 128) + i];
        for (int i = tid; i < 8 * 6 * 34; i += 256) {
            int ci = i / 204, r = (i / 34) % 6, c = i % 34;
            int gy = y0 - 1 + r, gx = x0 - 1 + c;
            float v = 0.f;
            if (gy >= 0 && gy < HH && gx >= 0 && gx < WW)
                v = x[(((size_t)b * CIN + cc * 8 + ci) * HH + gy) * WW + gx];
            sX[(ci * 6 + r) * 36 + c] = v;
        }
        __syncthreads();

#pragma unroll 2
        for (int ci = 0; ci < 8; ci++) {
#pragma unroll
            for (int ky = 0; ky < 3; ky++) {
                const float* xr = &sX[(ci * 6 + row + ky) * 36 + colq];
                float4 xa = *reinterpret_cast<const float4*>(xr);
                float4 xb = *reinterpret_cast<const float4*>(xr + 4);
                u64 xd[6];
                xd[0] = dup2(xa.x); xd[1] = dup2(xa.y);
                xd[2] = dup2(xa.z); xd[3] = dup2(xa.w);
                xd[4] = dup2(xb.x); xd[5] = dup2(xb.y);
#pragma unroll
                for (int kx = 0; kx < 3; kx++) {
                    const ulonglong2* wp = reinterpret_cast<const ulonglong2*>(
                        &sW[(ci * 9 + ky * 3 + kx) * 128 + cg * 16]);
                    ulonglong2 wA = wp[0];
                    ulonglong2 wB = wp[1];
                    ulonglong2 wC = wp[2];
                    ulonglong2 wD = wp[3];
#pragma unroll
                    for (int j = 0; j < 4; j++) {
                        u64 xv = xd[kx + j];
                        fma2(acc[0][j], wA.x, xv);
                        fma2(acc[1][j], wA.y, xv);
                        fma2(acc[2][j], wB.x, xv);
                        fma2(acc[3][j], wB.y, xv);
                        fma2(acc[4][j], wC.x, xv);
                        fma2(acc[5][j], wC.y, xv);
                        fma2(acc[6][j], wD.x, xv);
                        fma2(acc[7][j], wD.y, xv);
                    }
                }
            }
        }
    }

#pragma unroll
    for (int p = 0; p < 8; p++) {
        int c0 = cg * 16 + 2 * p;
        float b0 = bc[c0], b1 = bc[c0 + 1];
        float4 v0, v1;
        float2 f;
        f = unpk(acc[p][0]); v0.x = f.x + b0; v1.x = f.y + b1;
        f = unpk(acc[p][1]); v0.y = f.x + b0; v1.y = f.y + b1;
        f = unpk(acc[p][2]); v0.z = f.x + b0; v1.z = f.y + b1;
        f = unpk(acc[p][3]); v0.w = f.x + b0; v1.w = f.y + b1;
        size_t base = (((size_t)b * CO + c0) * HH + y0 + row) * WW + x0 + colq;
        *reinterpret_cast<float4*>(&g_h[base]) = v0;
        *reinterpret_cast<float4*>(&g_h[base + (size_t)HH * WW]) = v1;
    }
}

// ---------------------------------------------------------------------------
// Kernel 2 (FUSED): MC dropout mean/var + AU conv, single pass over h.
// Block: 256 threads = 8 rows x 32 cols pixel tile, 1 pixel/thread.
// Streams h in 32 chunks of 4 channels via haloed smem tile (10 x 34).
// ---------------------------------------------------------------------------
#define FILL_N 1360          // 4 ci * 10 rows * 34 cols
#define FILL_SLOTS 6

__global__ __launch_bounds__(256, 2) void mcau_kernel(
    const float* __restrict__ lms, const float* __restrict__ Wo,
    const float* __restrict__ bo, const float* __restrict__ masks,
    const float* __restrict__ Wa, const float* __restrict__ ba,
    float* __restrict__ out)
{
    __shared__ float sWm[128 * 64];     // [c][t][o], o fastest (32 KB)
    __shared__ float sWa[128 * 9 * 4];  // [(ci*9+k)*4 + o] (18 KB)
    __shared__ float sX[4 * 10 * 36];   // 4 ci x 10 rows x 34 cols, stride 36

    const int tid = threadIdx.x;
    for (int i = tid; i < 128 * 64; i += 256) {
        int c = i >> 6, t = (i >> 2) & 15, o = i & 3;
        sWm[i] = Wo[o * 128 + c] * masks[t * 128 + c];
    }
    for (int i = tid; i < 128 * 36; i += 256) {
        int ci = i / 36, rem = i % 36, k = rem >> 2, o = rem & 3;
        sWa[i] = Wa[(o * 128 + ci) * 9 + k];
    }

    const int b  = blockIdx.z;
    const int y0 = blockIdx.y * 8;
    const int x0 = blockIdx.x * 32;
    const int row = tid >> 5;        // 0..7
    const int col = tid & 31;        // 0..31

    // ---- precompute fill slots (hoists ALL div/mod out of the main loop) ----
    int smoff[FILL_SLOTS];
    int goff[FILL_SLOTS];            // g_h index for ci-chunk base, -1 = OOB/unused
#pragma unroll
    for (int s = 0; s < FILL_SLOTS; s++) {
        int i = tid + s * 256;
        smoff[s] = -1; goff[s] = -1;
        if (i < FILL_N) {
            int ci = i / 340, r = (i / 34) % 10, c = i % 34;
            int gy = y0 - 1 + r, gx = x0 - 1 + c;
            smoff[s] = (ci * 10 + r) * 36 + c;
            if (gy >= 0 && gy < HH && gx >= 0 && gx < WW)
                goff[s] = ((b * CO + ci) * HH + gy) * WW + gx;
        }
    }

    u64 mcA[16], mcB[16];            // mc accumulators: (o0,o1) / (o2,o3) per t
#pragma unroll
    for (int t = 0; t < 16; t++) { mcA[t] = 0ull; mcB[t] = 0ull; }
    u64 auA = 0ull, auB = 0ull;      // au accumulators: (o0,o1) / (o2,o3)

    for (int cc = 0; cc < 32; cc++) {
        __syncthreads();
        const int cshift = cc * 4 * HWP;
#pragma unroll
        for (int s = 0; s < FILL_SLOTS; s++) {
            if (smoff[s] >= 0) {
                float v = (goff[s] >= 0) ? __ldg(&g_h[goff[s] + cshift]) : 0.f;
                sX[smoff[s]] = v;
            }
        }
        __syncthreads();

#pragma unroll
        for (int ci = 0; ci < 4; ci++) {
            // --- mc: interior point ---
            float hv = sX[(ci * 10 + row + 1) * 36 + col + 1];
            u64 hd = dup2(hv);
            const ulonglong2* wr =
                reinterpret_cast<const ulonglong2*>(&sWm[(cc * 4 + ci) * 64]);
#pragma unroll
            for (int t = 0; t < 16; t++) {
                ulonglong2 w = wr[t];       // broadcast LDS.128
                fma2(mcA[t], w.x, hd);
                fma2(mcB[t], w.y, hd);
            }
            // --- au: 3x3 neighborhood ---
#pragma unroll
            for (int ky = 0; ky < 3; ky++) {
                const float* xr = &sX[(ci * 10 + row + ky) * 36 + col];
                float v0 = xr[0], v1 = xr[1], v2 = xr[2];
                const ulonglong2* wk = reinterpret_cast<const ulonglong2*>(
                    &sWa[((cc * 4 + ci) * 9 + ky * 3) * 4]);
                ulonglong2 w0 = wk[0], w1 = wk[1], w2 = wk[2];
                u64 x0d = dup2(v0), x1d = dup2(v1), x2d = dup2(v2);
                fma2(auA, w0.x, x0d); fma2(auB, w0.y, x0d);
                fma2(auA, w1.x, x1d); fma2(auB, w1.y, x1d);
                fma2(auA, w2.x, x2d); fma2(auB, w2.y, x2d);
            }
        }
    }

    // ---- epilogue ----
    const int pix  = (y0 + row) * WW + x0 + col;

    // mc: tanh, mean, unbiased var
    float a[16][4];
#pragma unroll
    for (int t = 0; t < 16; t++) {
        float2 f01 = unpk(mcA[t]);
        float2 f23 = unpk(mcB[t]);
        a[t][0] = f01.x; a[t][1] = f01.y; a[t][2] = f23.x; a[t][3] = f23.y;
    }
#pragma unroll
    for (int o = 0; o < 4; o++) {
        float bb = bo[o];
        float s[16];
        float sum = 0.f;
#pragma unroll
        for (int t = 0; t < 16; t++) {
            float v = tanhf(a[t][o] + bb);
            s[t] = v;
            sum += v;
        }
        float mn = sum * 0.0625f;
        float var = 0.f;
#pragma unroll
        for (int t = 0; t < 16; t++) {
            float d = s[t] - mn;
            var += d * d;
        }
        var *= (1.f / 15.f);
        int oidx = (b * 4 + o) * HWP + pix;
        out[NOUT + oidx]     = var;              // EU
        out[2 * NOUT + oidx] = mn + lms[oidx];   // mean
    }

    // au: sigmoid
    {
        float2 f01 = unpk(auA);
        float2 f23 = unpk(auB);
        float av[4] = { f01.x, f01.y, f23.x, f23.y };
#pragma unroll
        for (int o = 0; o < 4; o++) {
            float v = 1.f / (1.f + expf(-(av[o] + ba[o])));
            out[(b * 4 + o) * HWP + pix] = v;    // AU
        }
    }
}

// ---------------------------------------------------------------------------
extern "C" void kernel_launch(void* const* d_in, const int* in_sizes, int n_in,
                              void* d_out, int out_size) {
    const float* x     = (const float*)d_in[0];
    const float* lms   = (const float*)d_in[1];
    const float* Wc    = (const float*)d_in[2];
    const float* bc    = (const float*)d_in[3];
    const float* Wo    = (const float*)d_in[4];
    const float* bo    = (const float*)d_in[5];
    const float* Wa    = (const float*)d_in[6];
    const float* ba    = (const float*)d_in[7];
    const float* masks = (const float*)d_in[8];
    float* out = (float*)d_out;

    transpose_w<<<288, 256>>>(Wc);
    conv1_kernel<<<dim3(8, 64, 4), 256>>>(x, bc);
    mcau_kernel<<<dim3(8, 32, 4), 256>>>(lms, Wo, bo, masks, Wa, ba, out);
}

// round 5
// speedup vs baseline: 1.1800x; 1.1735x over previous
#include <cuda_runtime.h>

#define BB 4
#define CIN 64
#define CO 128
#define HH 256
#define WW 256
#define HWP 65536
#define NOUT (BB*4*HWP)   // 1048576

typedef unsigned long long u64;

// scratch: h = conv1(x)  [B, 128, 256, 256] fp32 = 128 MB
__device__ float g_h[(size_t)BB * CO * HWP];
// pre-transposed conv1 weights: [rk = ci*9+k][cout]  (576 x 128)
__device__ float g_Wt[576 * 128];

// ---- f32x2 helpers (packed 2xfp32 FMA — sm_103a FFMA2 path) -------------
__device__ __forceinline__ void fma2(u64& d, u64 a, u64 b) {
    asm("fma.rn.f32x2 %0, %1, %2, %0;" : "+l"(d) : "l"(a), "l"(b));
}
__device__ __forceinline__ u64 dup2(float x) {
    u64 d; asm("mov.b64 %0, {%1, %1};" : "=l"(d) : "f"(x)); return d;
}
__device__ __forceinline__ float2 unpk(u64 d) {
    float2 r; asm("mov.b64 {%0, %1}, %2;" : "=f"(r.x), "=f"(r.y) : "l"(d));
    return r;
}

// ---- fast-but-accurate transcendentals (abs err ~1e-7) -------------------
__device__ __forceinline__ float fast_tanh(float x) {
    // tanh(x) = 1 - 2/(1+exp(2x));  exp(2x) = ex2(x * 2*log2(e))
    float e;
    asm("ex2.approx.f32 %0, %1;" : "=f"(e) : "f"(x * 2.8853900817779268f));
    float r;
    asm("rcp.approx.f32 %0, %1;" : "=f"(r) : "f"(1.0f + e));
    return fmaf(-2.0f, r, 1.0f);
}
__device__ __forceinline__ float fast_sigmoid(float x) {
    float e;
    asm("ex2.approx.f32 %0, %1;" : "=f"(e) : "f"(-x * 1.4426950408889634f));
    float r;
    asm("rcp.approx.f32 %0, %1;" : "=f"(r) : "f"(1.0f + e));
    return r;
}

// ---- cp.async helpers -----------------------------------------------------
__device__ __forceinline__ void cpa16(unsigned saddr, const void* gaddr) {
    asm volatile("cp.async.ca.shared.global [%0], [%1], 16;"
                 :: "r"(saddr), "l"(gaddr));
}
__device__ __forceinline__ void cpa4z(unsigned saddr, const void* gaddr, int pred) {
    // zero-fills dst when pred==0 (src-size operand = 0)
    asm volatile("cp.async.ca.shared.global [%0], [%1], 4, %2;"
                 :: "r"(saddr), "l"(gaddr), "r"(pred ? 4 : 0));
}
__device__ __forceinline__ void cpa_commit() {
    asm volatile("cp.async.commit_group;");
}
__device__ __forceinline__ void cpa_wait_all() {
    asm volatile("cp.async.wait_group 0;");
}

// ---------------------------------------------------------------------------
// Kernel 0: transpose conv1 weights -> [rk][cout]
// ---------------------------------------------------------------------------
__global__ void transpose_w(const float* __restrict__ Wc) {
    int i = blockIdx.x * 256 + threadIdx.x;   // < 576*128
    int cout = i & 127, rk = i >> 7;
    g_Wt[rk * 128 + cout] = Wc[cout * 576 + rk];
}

// ---------------------------------------------------------------------------
// Kernel 1: 3x3 conv, 64 -> 128, pad 1, + bias.
// cp.async double-buffered; one __syncthreads per chunk; hoisted fill math.
// ---------------------------------------------------------------------------
#define XFILL_N 1632   // 8 ci * 6 rows * 34 cols
#define XSLOTS 7

__global__ __launch_bounds__(256, 2) void conv1_kernel(
    const float* __restrict__ x, const float* __restrict__ bc)
{
    __shared__ float sW[2][72 * 128];   // ping-pong [rk][cout]
    __shared__ float sX[2][8 * 6 * 36]; // ping-pong [ci][row][col], stride 36

    const int b  = blockIdx.z;
    const int y0 = blockIdx.y * 4;
    const int x0 = blockIdx.x * 32;
    const int tid  = threadIdx.x;
    const int cg   = tid >> 5;
    const int q    = tid & 31;
    const int row  = q >> 3;
    const int colq = (q & 7) * 4;

    // hoisted fill slots for x (smem float-offset, gmem base offset, validity)
    int xsm[XSLOTS]; int xg[XSLOTS]; int xok[XSLOTS];
#pragma unroll
    for (int s = 0; s < XSLOTS; s++) {
        int i = tid + s * 256;
        xsm[s] = -1; xg[s] = 0; xok[s] = 0;
        if (i < XFILL_N) {
            int ci = i / 204, r = (i / 34) % 6, c = i % 34;
            int gy = y0 - 1 + r, gx = x0 - 1 + c;
            xsm[s] = (ci * 6 + r) * 36 + c;
            if (gy >= 0 && gy < HH && gx >= 0 && gx < WW) {
                xok[s] = 1;
                xg[s] = ((b * CIN + ci) * HH + gy) * WW + gx;
            }
        }
    }

    unsigned sWb[2], sXb[2];
    sWb[0] = (unsigned)__cvta_generic_to_shared(&sW[0][0]);
    sWb[1] = (unsigned)__cvta_generic_to_shared(&sW[1][0]);
    sXb[0] = (unsigned)__cvta_generic_to_shared(&sX[0][0]);
    sXb[1] = (unsigned)__cvta_generic_to_shared(&sX[1][0]);

    // prefetch macro-ish lambda: chunk cc into buffer bf
    auto prefetch = [&](int cc, int bf) {
        const float* wsrc = g_Wt + cc * (72 * 128);
#pragma unroll
        for (int j = 0; j < 9; j++) {
            int o16 = j * 256 + tid;   // 16B units, 2304 total
            cpa16(sWb[bf] + o16 * 16, wsrc + o16 * 4);
        }
        const float* xsrc = x + (size_t)cc * 8 * HWP;
#pragma unroll
        for (int s = 0; s < XSLOTS; s++) {
            if (xsm[s] >= 0)
                cpa4z(sXb[bf] + xsm[s] * 4, xsrc + xg[s], xok[s]);
        }
        cpa_commit();
    };

    u64 acc[8][4];
#pragma unroll
    for (int p = 0; p < 8; p++)
#pragma unroll
        for (int j = 0; j < 4; j++) acc[p][j] = 0ull;

    prefetch(0, 0);

    for (int cc = 0; cc < 8; cc++) {
        const int bf = cc & 1;
        cpa_wait_all();        // chunk cc resident (this thread's copies)
        __syncthreads();       // all threads' copies done + prev compute done
        if (cc < 7) prefetch(cc + 1, bf ^ 1);

        const float* sWc = &sW[bf][0];
        const float* sXc = &sX[bf][0];
#pragma unroll 2
        for (int ci = 0; ci < 8; ci++) {
#pragma unroll
            for (int ky = 0; ky < 3; ky++) {
                const float* xr = &sXc[(ci * 6 + row + ky) * 36 + colq];
                float4 xa = *reinterpret_cast<const float4*>(xr);
                float4 xb = *reinterpret_cast<const float4*>(xr + 4);
                u64 xd[6];
                xd[0] = dup2(xa.x); xd[1] = dup2(xa.y);
                xd[2] = dup2(xa.z); xd[3] = dup2(xa.w);
                xd[4] = dup2(xb.x); xd[5] = dup2(xb.y);
#pragma unroll
                for (int kx = 0; kx < 3; kx++) {
                    const ulonglong2* wp = reinterpret_cast<const ulonglong2*>(
                        &sWc[(ci * 9 + ky * 3 + kx) * 128 + cg * 16]);
                    ulonglong2 wA = wp[0];
                    ulonglong2 wB = wp[1];
                    ulonglong2 wC = wp[2];
                    ulonglong2 wD = wp[3];
#pragma unroll
                    for (int j = 0; j < 4; j++) {
                        u64 xv = xd[kx + j];
                        fma2(acc[0][j], wA.x, xv);
                        fma2(acc[1][j], wA.y, xv);
                        fma2(acc[2][j], wB.x, xv);
                        fma2(acc[3][j], wB.y, xv);
                        fma2(acc[4][j], wC.x, xv);
                        fma2(acc[5][j], wC.y, xv);
                        fma2(acc[6][j], wD.x, xv);
                        fma2(acc[7][j], wD.y, xv);
                    }
                }
            }
        }
        __syncthreads();       // compute(cc) done before buffer bf is refilled
    }

#pragma unroll
    for (int p = 0; p < 8; p++) {
        int c0 = cg * 16 + 2 * p;
        float b0 = bc[c0], b1 = bc[c0 + 1];
        float4 v0, v1;
        float2 f;
        f = unpk(acc[p][0]); v0.x = f.x + b0; v1.x = f.y + b1;
        f = unpk(acc[p][1]); v0.y = f.x + b0; v1.y = f.y + b1;
        f = unpk(acc[p][2]); v0.z = f.x + b0; v1.z = f.y + b1;
        f = unpk(acc[p][3]); v0.w = f.x + b0; v1.w = f.y + b1;
        size_t base = (((size_t)b * CO + c0) * HH + y0 + row) * WW + x0 + colq;
        *reinterpret_cast<float4*>(&g_h[base]) = v0;
        *reinterpret_cast<float4*>(&g_h[base + (size_t)HH * WW]) = v1;
    }
}

// ---------------------------------------------------------------------------
// Kernel 2 (FUSED): MC dropout mean/var + AU conv, single pass over h.
// Epilogue now uses ex2/rcp-based tanh & sigmoid.
// ---------------------------------------------------------------------------
#define FILL_N 1360          // 4 ci * 10 rows * 34 cols
#define FILL_SLOTS 6

__global__ __launch_bounds__(256, 2) void mcau_kernel(
    const float* __restrict__ lms, const float* __restrict__ Wo,
    const float* __restrict__ bo, const float* __restrict__ masks,
    const float* __restrict__ Wa, const float* __restrict__ ba,
    float* __restrict__ out)
{
    __shared__ float sWm[128 * 64];     // [c][t][o], o fastest (32 KB)
    __shared__ float sWa[128 * 9 * 4];  // [(ci*9+k)*4 + o] (18 KB)
    __shared__ float sX[4 * 10 * 36];   // 4 ci x 10 rows x 34 cols, stride 36

    const int tid = threadIdx.x;
    for (int i = tid; i < 128 * 64; i += 256) {
        int c = i >> 6, t = (i >> 2) & 15, o = i & 3;
        sWm[i] = Wo[o * 128 + c] * masks[t * 128 + c];
    }
    for (int i = tid; i < 128 * 36; i += 256) {
        int ci = i / 36, rem = i % 36, k = rem >> 2, o = rem & 3;
        sWa[i] = Wa[(o * 128 + ci) * 9 + k];
    }

    const int b  = blockIdx.z;
    const int y0 = blockIdx.y * 8;
    const int x0 = blockIdx.x * 32;
    const int row = tid >> 5;        // 0..7
    const int col = tid & 31;        // 0..31

    int smoff[FILL_SLOTS];
    int goff[FILL_SLOTS];
#pragma unroll
    for (int s = 0; s < FILL_SLOTS; s++) {
        int i = tid + s * 256;
        smoff[s] = -1; goff[s] = -1;
        if (i < FILL_N) {
            int ci = i / 340, r = (i / 34) % 10, c = i % 34;
            int gy = y0 - 1 + r, gx = x0 - 1 + c;
            smoff[s] = (ci * 10 + r) * 36 + c;
            if (gy >= 0 && gy < HH && gx >= 0 && gx < WW)
                goff[s] = ((b * CO + ci) * HH + gy) * WW + gx;
        }
    }

    u64 mcA[16], mcB[16];
#pragma unroll
    for (int t = 0; t < 16; t++) { mcA[t] = 0ull; mcB[t] = 0ull; }
    u64 auA = 0ull, auB = 0ull;

    for (int cc = 0; cc < 32; cc++) {
        __syncthreads();
        const int cshift = cc * 4 * HWP;
#pragma unroll
        for (int s = 0; s < FILL_SLOTS; s++) {
            if (smoff[s] >= 0) {
                float v = (goff[s] >= 0) ? __ldg(&g_h[goff[s] + cshift]) : 0.f;
                sX[smoff[s]] = v;
            }
        }
        __syncthreads();

#pragma unroll
        for (int ci = 0; ci < 4; ci++) {
            float hv = sX[(ci * 10 + row + 1) * 36 + col + 1];
            u64 hd = dup2(hv);
            const ulonglong2* wr =
                reinterpret_cast<const ulonglong2*>(&sWm[(cc * 4 + ci) * 64]);
#pragma unroll
            for (int t = 0; t < 16; t++) {
                ulonglong2 w = wr[t];
                fma2(mcA[t], w.x, hd);
                fma2(mcB[t], w.y, hd);
            }
#pragma unroll
            for (int ky = 0; ky < 3; ky++) {
                const float* xr = &sX[(ci * 10 + row + ky) * 36 + col];
                float v0 = xr[0], v1 = xr[1], v2 = xr[2];
                const ulonglong2* wk = reinterpret_cast<const ulonglong2*>(
                    &sWa[((cc * 4 + ci) * 9 + ky * 3) * 4]);
                ulonglong2 w0 = wk[0], w1 = wk[1], w2 = wk[2];
                u64 x0d = dup2(v0), x1d = dup2(v1), x2d = dup2(v2);
                fma2(auA, w0.x, x0d); fma2(auB, w0.y, x0d);
                fma2(auA, w1.x, x1d); fma2(auB, w1.y, x1d);
                fma2(auA, w2.x, x2d); fma2(auB, w2.y, x2d);
            }
        }
    }

    const int pix  = (y0 + row) * WW + x0 + col;

    float a[16][4];
#pragma unroll
    for (int t = 0; t < 16; t++) {
        float2 f01 = unpk(mcA[t]);
        float2 f23 = unpk(mcB[t]);
        a[t][0] = f01.x; a[t][1] = f01.y; a[t][2] = f23.x; a[t][3] = f23.y;
    }
#pragma unroll
    for (int o = 0; o < 4; o++) {
        float bb = bo[o];
        float s[16];
        float sum = 0.f;
#pragma unroll
        for (int t = 0; t < 16; t++) {
            float v = fast_tanh(a[t][o] + bb);
            s[t] = v;
            sum += v;
        }
        float mn = sum * 0.0625f;
        float var = 0.f;
#pragma unroll
        for (int t = 0; t < 16; t++) {
            float d = s[t] - mn;
            var += d * d;
        }
        var *= (1.f / 15.f);
        int oidx = (b * 4 + o) * HWP + pix;
        out[NOUT + oidx]     = var;              // EU
        out[2 * NOUT + oidx] = mn + lms[oidx];   // mean
    }

    {
        float2 f01 = unpk(auA);
        float2 f23 = unpk(auB);
        float av[4] = { f01.x, f01.y, f23.x, f23.y };
#pragma unroll
        for (int o = 0; o < 4; o++)
            out[(b * 4 + o) * HWP + pix] = fast_sigmoid(av[o] + ba[o]);  // AU
    }
}

// ---------------------------------------------------------------------------
extern "C" void kernel_launch(void* const* d_in, const int* in_sizes, int n_in,
                              void* d_out, int out_size) {
    const float* x     = (const float*)d_in[0];
    const float* lms   = (const float*)d_in[1];
    const float* Wc    = (const float*)d_in[2];
    const float* bc    = (const float*)d_in[3];
    const float* Wo    = (const float*)d_in[4];
    const float* bo    = (const float*)d_in[5];
    const float* Wa    = (const float*)d_in[6];
    const float* ba    = (const float*)d_in[7];
    const float* masks = (const float*)d_in[8];
    float* out = (float*)d_out;

    transpose_w<<<288, 256>>>(Wc);
    conv1_kernel<<<dim3(8, 64, 4), 256>>>(x, bc);
    mcau_kernel<<<dim3(8, 32, 4), 256>>>(lms, Wo, bo, masks, Wa, ba, out);
}

// round 6
// speedup vs baseline: 1.2527x; 1.0616x over previous
#include <cuda_runtime.h>

#define BB 4
#define CIN 64
#define CO 128
#define HH 256
#define WW 256
#define HWP 65536
#define NOUT (BB*4*HWP)   // 1048576

typedef unsigned long long u64;

// scratch: h = conv1(x)  [B, 128, 256, 256] fp32 = 128 MB
__device__ float g_h[(size_t)BB * CO * HWP];
// pre-transposed conv1 weights: [rk = ci*9+k][cout]  (576 x 128)
__device__ float g_Wt[576 * 128];

// ---- f32x2 helpers (packed 2xfp32 FMA — sm_103a FFMA2 path) -------------
__device__ __forceinline__ void fma2(u64& d, u64 a, u64 b) {
    asm("fma.rn.f32x2 %0, %1, %2, %0;" : "+l"(d) : "l"(a), "l"(b));
}
__device__ __forceinline__ u64 dup2(float x) {
    u64 d; asm("mov.b64 %0, {%1, %1};" : "=l"(d) : "f"(x)); return d;
}
__device__ __forceinline__ float2 unpk(u64 d) {
    float2 r; asm("mov.b64 {%0, %1}, %2;" : "=f"(r.x), "=f"(r.y) : "l"(d));
    return r;
}

// ---- fast-but-accurate transcendentals (abs err ~1e-7) -------------------
__device__ __forceinline__ float fast_tanh(float x) {
    float e;
    asm("ex2.approx.f32 %0, %1;" : "=f"(e) : "f"(x * 2.8853900817779268f));
    float r;
    asm("rcp.approx.f32 %0, %1;" : "=f"(r) : "f"(1.0f + e));
    return fmaf(-2.0f, r, 1.0f);
}
__device__ __forceinline__ float fast_sigmoid(float x) {
    float e;
    asm("ex2.approx.f32 %0, %1;" : "=f"(e) : "f"(-x * 1.4426950408889634f));
    float r;
    asm("rcp.approx.f32 %0, %1;" : "=f"(r) : "f"(1.0f + e));
    return r;
}

// ---- cp.async helpers -----------------------------------------------------
__device__ __forceinline__ void cpa16(unsigned saddr, const void* gaddr) {
    asm volatile("cp.async.ca.shared.global [%0], [%1], 16;"
                 :: "r"(saddr), "l"(gaddr));
}
__device__ __forceinline__ void cpa4z(unsigned saddr, const void* gaddr, int pred) {
    asm volatile("cp.async.ca.shared.global [%0], [%1], 4, %2;"
                 :: "r"(saddr), "l"(gaddr), "r"(pred ? 4 : 0));
}
__device__ __forceinline__ void cpa_commit() {
    asm volatile("cp.async.commit_group;");
}
__device__ __forceinline__ void cpa_wait_all() {
    asm volatile("cp.async.wait_group 0;");
}

// ---------------------------------------------------------------------------
// Kernel 0: transpose conv1 weights -> [rk][cout]
// ---------------------------------------------------------------------------
__global__ void transpose_w(const float* __restrict__ Wc) {
    int i = blockIdx.x * 256 + threadIdx.x;   // < 576*128
    int cout = i & 127, rk = i >> 7;
    g_Wt[rk * 128 + cout] = Wc[cout * 576 + rk];
}

// ---------------------------------------------------------------------------
// Kernel 1: 3x3 conv, 64 -> 128, pad 1, + bias. (unchanged from R5)
// ---------------------------------------------------------------------------
#define XFILL_N 1632   // 8 ci * 6 rows * 34 cols
#define XSLOTS 7

__global__ __launch_bounds__(256, 2) void conv1_kernel(
    const float* __restrict__ x, const float* __restrict__ bc)
{
    __shared__ float sW[2][72 * 128];
    __shared__ float sX[2][8 * 6 * 36];

    const int b  = blockIdx.z;
    const int y0 = blockIdx.y * 4;
    const int x0 = blockIdx.x * 32;
    const int tid  = threadIdx.x;
    const int cg   = tid >> 5;
    const int q    = tid & 31;
    const int row  = q >> 3;
    const int colq = (q & 7) * 4;

    int xsm[XSLOTS]; int xg[XSLOTS]; int xok[XSLOTS];
#pragma unroll
    for (int s = 0; s < XSLOTS; s++) {
        int i = tid + s * 256;
        xsm[s] = -1; xg[s] = 0; xok[s] = 0;
        if (i < XFILL_N) {
            int ci = i / 204, r = (i / 34) % 6, c = i % 34;
            int gy = y0 - 1 + r, gx = x0 - 1 + c;
            xsm[s] = (ci * 6 + r) * 36 + c;
            if (gy >= 0 && gy < HH && gx >= 0 && gx < WW) {
                xok[s] = 1;
                xg[s] = ((b * CIN + ci) * HH + gy) * WW + gx;
            }
        }
    }

    unsigned sWb[2], sXb[2];
    sWb[0] = (unsigned)__cvta_generic_to_shared(&sW[0][0]);
    sWb[1] = (unsigned)__cvta_generic_to_shared(&sW[1][0]);
    sXb[0] = (unsigned)__cvta_generic_to_shared(&sX[0][0]);
    sXb[1] = (unsigned)__cvta_generic_to_shared(&sX[1][0]);

    auto prefetch = [&](int cc, int bf) {
        const float* wsrc = g_Wt + cc * (72 * 128);
#pragma unroll
        for (int j = 0; j < 9; j++) {
            int o16 = j * 256 + tid;
            cpa16(sWb[bf] + o16 * 16, wsrc + o16 * 4);
        }
        const float* xsrc = x + (size_t)cc * 8 * HWP;
#pragma unroll
        for (int s = 0; s < XSLOTS; s++) {
            if (xsm[s] >= 0)
                cpa4z(sXb[bf] + xsm[s] * 4, xsrc + xg[s], xok[s]);
        }
        cpa_commit();
    };

    u64 acc[8][4];
#pragma unroll
    for (int p = 0; p < 8; p++)
#pragma unroll
        for (int j = 0; j < 4; j++) acc[p][j] = 0ull;

    prefetch(0, 0);

    for (int cc = 0; cc < 8; cc++) {
        const int bf = cc & 1;
        cpa_wait_all();
        __syncthreads();
        if (cc < 7) prefetch(cc + 1, bf ^ 1);

        const float* sWc = &sW[bf][0];
        const float* sXc = &sX[bf][0];
#pragma unroll 2
        for (int ci = 0; ci < 8; ci++) {
#pragma unroll
            for (int ky = 0; ky < 3; ky++) {
                const float* xr = &sXc[(ci * 6 + row + ky) * 36 + colq];
                float4 xa = *reinterpret_cast<const float4*>(xr);
                float4 xb = *reinterpret_cast<const float4*>(xr + 4);
                u64 xd[6];
                xd[0] = dup2(xa.x); xd[1] = dup2(xa.y);
                xd[2] = dup2(xa.z); xd[3] = dup2(xa.w);
                xd[4] = dup2(xb.x); xd[5] = dup2(xb.y);
#pragma unroll
                for (int kx = 0; kx < 3; kx++) {
                    const ulonglong2* wp = reinterpret_cast<const ulonglong2*>(
                        &sWc[(ci * 9 + ky * 3 + kx) * 128 + cg * 16]);
                    ulonglong2 wA = wp[0];
                    ulonglong2 wB = wp[1];
                    ulonglong2 wC = wp[2];
                    ulonglong2 wD = wp[3];
#pragma unroll
                    for (int j = 0; j < 4; j++) {
                        u64 xv = xd[kx + j];
                        fma2(acc[0][j], wA.x, xv);
                        fma2(acc[1][j], wA.y, xv);
                        fma2(acc[2][j], wB.x, xv);
                        fma2(acc[3][j], wB.y, xv);
                        fma2(acc[4][j], wC.x, xv);
                        fma2(acc[5][j], wC.y, xv);
                        fma2(acc[6][j], wD.x, xv);
                        fma2(acc[7][j], wD.y, xv);
                    }
                }
            }
        }
        __syncthreads();
    }

#pragma unroll
    for (int p = 0; p < 8; p++) {
        int c0 = cg * 16 + 2 * p;
        float b0 = bc[c0], b1 = bc[c0 + 1];
        float4 v0, v1;
        float2 f;
        f = unpk(acc[p][0]); v0.x = f.x + b0; v1.x = f.y + b1;
        f = unpk(acc[p][1]); v0.y = f.x + b0; v1.y = f.y + b1;
        f = unpk(acc[p][2]); v0.z = f.x + b0; v1.z = f.y + b1;
        f = unpk(acc[p][3]); v0.w = f.x + b0; v1.w = f.y + b1;
        size_t base = (((size_t)b * CO + c0) * HH + y0 + row) * WW + x0 + colq;
        *reinterpret_cast<float4*>(&g_h[base]) = v0;
        *reinterpret_cast<float4*>(&g_h[base + (size_t)HH * WW]) = v1;
    }
}

// ---------------------------------------------------------------------------
// Kernel 2 (FUSED): MC mean/var + AU conv, single pass over h.
// NOW: cp.async double-buffered h tile (same pipeline as conv1).
// ---------------------------------------------------------------------------
#define FILL_N 1360          // 4 ci * 10 rows * 34 cols
#define FILL_SLOTS 6

__global__ __launch_bounds__(256, 2) void mcau_kernel(
    const float* __restrict__ lms, const float* __restrict__ Wo,
    const float* __restrict__ bo, const float* __restrict__ masks,
    const float* __restrict__ Wa, const float* __restrict__ ba,
    float* __restrict__ out)
{
    __shared__ float sWm[128 * 64];     // [c][t][o] (32 KB)
    __shared__ float sWa[128 * 9 * 4];  // (18 KB)
    __shared__ float sX[2][4 * 10 * 36]; // ping-pong h tile (11.5 KB)

    const int tid = threadIdx.x;
    for (int i = tid; i < 128 * 64; i += 256) {
        int c = i >> 6, t = (i >> 2) & 15, o = i & 3;
        sWm[i] = Wo[o * 128 + c] * masks[t * 128 + c];
    }
    for (int i = tid; i < 128 * 36; i += 256) {
        int ci = i / 36, rem = i % 36, k = rem >> 2, o = rem & 3;
        sWa[i] = Wa[(o * 128 + ci) * 9 + k];
    }

    const int b  = blockIdx.z;
    const int y0 = blockIdx.y * 8;
    const int x0 = blockIdx.x * 32;
    const int row = tid >> 5;
    const int col = tid & 31;

    int smoff[FILL_SLOTS]; int goff[FILL_SLOTS]; int gok[FILL_SLOTS];
#pragma unroll
    for (int s = 0; s < FILL_SLOTS; s++) {
        int i = tid + s * 256;
        smoff[s] = -1; goff[s] = 0; gok[s] = 0;
        if (i < FILL_N) {
            int ci = i / 340, r = (i / 34) % 10, c = i % 34;
            int gy = y0 - 1 + r, gx = x0 - 1 + c;
            smoff[s] = (ci * 10 + r) * 36 + c;
            if (gy >= 0 && gy < HH && gx >= 0 && gx < WW) {
                gok[s] = 1;
                goff[s] = ((b * CO + ci) * HH + gy) * WW + gx;
            }
        }
    }

    unsigned sXb[2];
    sXb[0] = (unsigned)__cvta_generic_to_shared(&sX[0][0]);
    sXb[1] = (unsigned)__cvta_generic_to_shared(&sX[1][0]);

    auto prefetch = [&](int cc, int bf) {
        const float* hsrc = g_h + (size_t)cc * 4 * HWP;
#pragma unroll
        for (int s = 0; s < FILL_SLOTS; s++) {
            if (smoff[s] >= 0)
                cpa4z(sXb[bf] + smoff[s] * 4, hsrc + goff[s], gok[s]);
        }
        cpa_commit();
    };

    u64 mcA[16], mcB[16];
#pragma unroll
    for (int t = 0; t < 16; t++) { mcA[t] = 0ull; mcB[t] = 0ull; }
    u64 auA = 0ull, auB = 0ull;

    prefetch(0, 0);
    __syncthreads();   // weight smem ready (overlaps with first prefetch)

    for (int cc = 0; cc < 32; cc++) {
        const int bf = cc & 1;
        cpa_wait_all();
        __syncthreads();
        if (cc < 31) prefetch(cc + 1, bf ^ 1);

        const float* sXc = &sX[bf][0];
#pragma unroll
        for (int ci = 0; ci < 4; ci++) {
            // --- mc: interior point ---
            float hv = sXc[(ci * 10 + row + 1) * 36 + col + 1];
            u64 hd = dup2(hv);
            const ulonglong2* wr =
                reinterpret_cast<const ulonglong2*>(&sWm[(cc * 4 + ci) * 64]);
#pragma unroll
            for (int t = 0; t < 16; t++) {
                ulonglong2 w = wr[t];       // broadcast LDS.128
                fma2(mcA[t], w.x, hd);
                fma2(mcB[t], w.y, hd);
            }
            // --- au: 3x3 neighborhood ---
#pragma unroll
            for (int ky = 0; ky < 3; ky++) {
                const float* xr = &sXc[(ci * 10 + row + ky) * 36 + col];
                float v0 = xr[0], v1 = xr[1], v2 = xr[2];
                const ulonglong2* wk = reinterpret_cast<const ulonglong2*>(
                    &sWa[((cc * 4 + ci) * 9 + ky * 3) * 4]);
                ulonglong2 w0 = wk[0], w1 = wk[1], w2 = wk[2];
                u64 x0d = dup2(v0), x1d = dup2(v1), x2d = dup2(v2);
                fma2(auA, w0.x, x0d); fma2(auB, w0.y, x0d);
                fma2(auA, w1.x, x1d); fma2(auB, w1.y, x1d);
                fma2(auA, w2.x, x2d); fma2(auB, w2.y, x2d);
            }
        }
        __syncthreads();   // compute(cc) done before bf refilled at cc+2
    }

    const int pix  = (y0 + row) * WW + x0 + col;

    float a[16][4];
#pragma unroll
    for (int t = 0; t < 16; t++) {
        float2 f01 = unpk(mcA[t]);
        float2 f23 = unpk(mcB[t]);
        a[t][0] = f01.x; a[t][1] = f01.y; a[t][2] = f23.x; a[t][3] = f23.y;
    }
#pragma unroll
    for (int o = 0; o < 4; o++) {
        float bb = bo[o];
        float s[16];
        float sum = 0.f;
#pragma unroll
        for (int t = 0; t < 16; t++) {
            float v = fast_tanh(a[t][o] + bb);
            s[t] = v;
            sum += v;
        }
        float mn = sum * 0.0625f;
        float var = 0.f;
#pragma unroll
        for (int t = 0; t < 16; t++) {
            float d = s[t] - mn;
            var += d * d;
        }
        var *= (1.f / 15.f);
        int oidx = (b * 4 + o) * HWP + pix;
        out[NOUT + oidx]     = var;              // EU
        out[2 * NOUT + oidx] = mn + lms[oidx];   // mean
    }

    {
        float2 f01 = unpk(auA);
        float2 f23 = unpk(auB);
        float av[4] = { f01.x, f01.y, f23.x, f23.y };
#pragma unroll
        for (int o = 0; o < 4; o++)
            out[(b * 4 + o) * HWP + pix] = fast_sigmoid(av[o] + ba[o]);  // AU
    }
}

// ---------------------------------------------------------------------------
extern "C" void kernel_launch(void* const* d_in, const int* in_sizes, int n_in,
                              void* d_out, int out_size) {
    const float* x     = (const float*)d_in[0];
    const float* lms   = (const float*)d_in[1];
    const float* Wc    = (const float*)d_in[2];
    const float* bc    = (const float*)d_in[3];
    const float* Wo    = (const float*)d_in[4];
    const float* bo    = (const float*)d_in[5];
    const float* Wa    = (const float*)d_in[6];
    const float* ba    = (const float*)d_in[7];
    const float* masks = (const float*)d_in[8];
    float* out = (float*)d_out;

    transpose_w<<<288, 256>>>(Wc);
    conv1_kernel<<<dim3(8, 64, 4), 256>>>(x, bc);
    mcau_kernel<<<dim3(8, 32, 4), 256>>>(lms, Wo, bo, masks, Wa, ba, out);
}

// round 8
// speedup vs baseline: 1.5235x; 1.2162x over previous
#include <cuda_runtime.h>
#include <cuda_bf16.h>

#define BB 4
#define CIN 64
#define CO 128
#define HH 256
#define WW 256
#define HWP 65536
#define NOUT (BB*4*HWP)   // 1048576

typedef unsigned long long u64;

// scratch
__device__ float g_h[(size_t)BB * CO * HWP];                          // conv1 out [b][cout][pix]
__device__ __align__(256) unsigned short g_xh[(size_t)BB * HWP * 64]; // x hi, [b][pix][ci] bf16
__device__ __align__(256) unsigned short g_xl[(size_t)BB * HWP * 64]; // x lo
__device__ __align__(256) unsigned char  g_wp[18 * 16384];            // 9 taps x {hi,lo}, swizzled [cout][ci]

// ---- f32x2 helpers --------------------------------------------------------
__device__ __forceinline__ void fma2(u64& d, u64 a, u64 b) {
    asm("fma.rn.f32x2 %0, %1, %2, %0;" : "+l"(d) : "l"(a), "l"(b));
}
__device__ __forceinline__ u64 dup2(float x) {
    u64 d; asm("mov.b64 %0, {%1, %1};" : "=l"(d) : "f"(x)); return d;
}
__device__ __forceinline__ float2 unpk(u64 d) {
    float2 r; asm("mov.b64 {%0, %1}, %2;" : "=f"(r.x), "=f"(r.y) : "l"(d));
    return r;
}

// ---- fast transcendentals (abs err ~1e-7) ---------------------------------
__device__ __forceinline__ float fast_tanh(float x) {
    float e;
    asm("ex2.approx.f32 %0, %1;" : "=f"(e) : "f"(x * 2.8853900817779268f));
    float r;
    asm("rcp.approx.f32 %0, %1;" : "=f"(r) : "f"(1.0f + e));
    return fmaf(-2.0f, r, 1.0f);
}
__device__ __forceinline__ float fast_sigmoid(float x) {
    float e;
    asm("ex2.approx.f32 %0, %1;" : "=f"(e) : "f"(-x * 1.4426950408889634f));
    float r;
    asm("rcp.approx.f32 %0, %1;" : "=f"(r) : "f"(1.0f + e));
    return r;
}

// ---- cp.async helpers -----------------------------------------------------
__device__ __forceinline__ void cpa16(unsigned saddr, const void* gaddr) {
    asm volatile("cp.async.cg.shared.global [%0], [%1], 16;"
                 :: "r"(saddr), "l"(gaddr));
}
__device__ __forceinline__ void cpa16z(unsigned saddr, const void* gaddr, int ok) {
    asm volatile("cp.async.cg.shared.global [%0], [%1], 16, %2;"
                 :: "r"(saddr), "l"(gaddr), "r"(ok ? 16 : 0));
}
__device__ __forceinline__ void cpa4z(unsigned saddr, const void* gaddr, int pred) {
    asm volatile("cp.async.ca.shared.global [%0], [%1], 4, %2;"
                 :: "r"(saddr), "l"(gaddr), "r"(pred ? 4 : 0));
}
__device__ __forceinline__ void cpa_commit() {
    asm volatile("cp.async.commit_group;");
}
__device__ __forceinline__ void cpa_wait_all() {
    asm volatile("cp.async.wait_group 0;");
}

// ---- legacy tensor core: ldmatrix + mma.sync (NOT arch-gated) --------------
__device__ __forceinline__ void ldmx4(unsigned& r0, unsigned& r1,
                                      unsigned& r2, unsigned& r3, unsigned a) {
    asm volatile("ldmatrix.sync.aligned.m8n8.x4.shared.b16 {%0,%1,%2,%3}, [%4];"
                 : "=r"(r0), "=r"(r1), "=r"(r2), "=r"(r3) : "r"(a));
}
__device__ __forceinline__ void mma_bf16(float* d, unsigned a0, unsigned a1,
                                         unsigned a2, unsigned a3,
                                         unsigned b0, unsigned b1) {
    asm volatile(
        "mma.sync.aligned.m16n8k16.row.col.f32.bf16.bf16.f32 "
        "{%0,%1,%2,%3}, {%4,%5,%6,%7}, {%8,%9}, {%0,%1,%2,%3};"
        : "+f"(d[0]), "+f"(d[1]), "+f"(d[2]), "+f"(d[3])
        : "r"(a0), "r"(a1), "r"(a2), "r"(a3), "r"(b0), "r"(b1));
}
__device__ __forceinline__ int swz(int off) { return off ^ ((off >> 3) & 0x70); }

// ---------------------------------------------------------------------------
// Prep 1: split conv weights to bf16 hi/lo, SW128-swizzled [cout][ci] tiles.
// ---------------------------------------------------------------------------
__global__ void wprep(const float* __restrict__ Wc) {
    int i = blockIdx.x * 256 + threadIdx.x;   // < 73728 = 9*128*64
    int tap = i >> 13, rem = i & 8191, cout = rem >> 6, ci = rem & 63;
    float v = Wc[cout * 576 + ci * 9 + tap];
    __nv_bfloat16 h = __float2bfloat16(v);
    float hf = __bfloat162float(h);
    __nv_bfloat16 l = __float2bfloat16(v - hf);
    int sw = swz(cout * 128 + ci * 2);
    *(unsigned short*)(g_wp + (tap * 2 + 0) * 16384 + sw) =
        *reinterpret_cast<unsigned short*>(&h);
    *(unsigned short*)(g_wp + (tap * 2 + 1) * 16384 + sw) =
        *reinterpret_cast<unsigned short*>(&l);
}

// ---------------------------------------------------------------------------
// Prep 2: transpose x to pixel-major bf16 hi/lo: g_x{h,l}[b][pix][ci]
// ---------------------------------------------------------------------------
__global__ void xprep(const float* __restrict__ x) {
    __shared__ unsigned short shh[32 * 66], shl[32 * 66];
    const int bx = blockIdx.x;
    const int b = bx >> 11;
    const int px0 = (bx & 2047) * 32;
    const int tid = threadIdx.x;
    for (int i = tid; i < 2048; i += 256) {
        int ci = i >> 5, p = i & 31;
        float v = x[(((size_t)b * 64 + ci) << 16) + px0 + p];
        __nv_bfloat16 h = __float2bfloat16(v);
        float hf = __bfloat162float(h);
        __nv_bfloat16 l = __float2bfloat16(v - hf);
        shh[p * 66 + ci] = *reinterpret_cast<unsigned short*>(&h);
        shl[p * 66 + ci] = *reinterpret_cast<unsigned short*>(&l);
    }
    __syncthreads();
    for (int i = tid; i < 1024; i += 256) {
        int p = i >> 5, j = i & 31;
        unsigned vh = shh[p * 66 + 2 * j] | ((unsigned)shh[p * 66 + 2 * j + 1] << 16);
        unsigned vl = shl[p * 66 + 2 * j] | ((unsigned)shl[p * 66 + 2 * j + 1] << 16);
        size_t rb = ((size_t)b * HWP + px0 + p) * 32 + j;
        reinterpret_cast<unsigned*>(g_xh)[rb] = vh;
        reinterpret_cast<unsigned*>(g_xl)[rb] = vl;
    }
}

// ---------------------------------------------------------------------------
// Kernel 1: conv1 via mma.sync bf16 3-pass. CTA = 128 cout x 128 px.
// B (x, 3 ky-rows x 130 px, hi+lo) loaded once; A (weights) streamed per tap.
// ---------------------------------------------------------------------------
#define SB_BYTES 49920          // 390 rows * 128 B
#define CV_SMEM (2*SB_BYTES + 65536 + 1024)

__global__ __launch_bounds__(256, 1) void conv_hmma(const float* __restrict__ bc) {
    extern __shared__ unsigned char dsm[];
    const int tid = threadIdx.x;
    const int w = tid >> 5, lane = tid & 31;
    const int blk = blockIdx.x;
    const int xh = blk & 1, y = (blk >> 1) & 255, b = blk >> 9;
    const int x0 = xh * 128;

    unsigned raw = (unsigned)__cvta_generic_to_shared(dsm);
    unsigned base = (raw + 1023) & ~1023u;
    unsigned sBh = base, sBl = base + SB_BYTES, sA = base + 2 * SB_BYTES;

    // ---- B fill (once): 3 ky-rows x 130 px x 128B, hi + lo, zfill at edges
    for (int i = tid; i < 6240; i += 256) {
        int half = (i >= 3120);
        int idx = half ? i - 3120 : i;
        int r = idx >> 3, c = idx & 7;           // r < 390, c = 16B chunk
        int ky = r / 130, p = r % 130;
        int gy = y + ky - 1, gx = x0 + p - 1;
        int ok = (gy >= 0 && gy < HH && gx >= 0 && gx < WW);
        const unsigned char* src =
            (half ? (const unsigned char*)g_xl : (const unsigned char*)g_xh)
            + ((size_t)(b * HWP + (ok ? gy * WW + gx : 0)) * 128) + c * 16;
        cpa16z((half ? sBl : sBh) + swz(r * 128 + c * 16), src, ok);
    }
    cpa_commit();

    // ---- A prefetch: tap t -> buffer buf (32 KB: hi 16K + lo 16K contiguous)
    auto prefA = [&](int t, int buf) {
        const unsigned char* src = g_wp + t * 32768;
        unsigned dst = sA + buf * 32768;
#pragma unroll
        for (int j = 0; j < 8; j++) {
            int off = (tid * 8 + j) * 16;
            cpa16(dst + off, src + off);
        }
        cpa_commit();
    };
    prefA(0, 0);

    // per-thread ldmatrix address components
    const int arow = (16 * w + (lane & 7) + ((lane >> 3) & 1) * 8) * 128
                   + ((lane >> 4) & 1) * 16;             // A: [cout][ci]
    const int pxl  = (lane & 7) + ((lane >> 4) & 1) * 8; // B row within 16-px pair
    const int kextB = ((lane >> 3) & 1) * 16;

    float d[16][4];
#pragma unroll
    for (int j = 0; j < 16; j++)
#pragma unroll
        for (int q = 0; q < 4; q++) d[j][q] = 0.f;

    for (int t = 0; t < 9; t++) {
        cpa_wait_all();
        __syncthreads();
        if (t < 8) prefA(t + 1, (t + 1) & 1);

        const int rowb = (t / 3) * 130 + (t % 3);   // ky*130 + kx
        unsigned Ahi = sA + (t & 1) * 32768;
#pragma unroll
        for (int pass = 0; pass < 3; pass++) {
            unsigned Abase = (pass == 2) ? (Ahi + 16384) : Ahi;
            unsigned Bbase = (pass == 1) ? sBl : sBh;
#pragma unroll
            for (int k = 0; k < 4; k++) {
                unsigned a0, a1, a2, a3;
                ldmx4(a0, a1, a2, a3, Abase + swz(arow + k * 32));
                const int bc0 = (rowb + pxl) * 128 + k * 32 + kextB;
#pragma unroll
                for (int jp = 0; jp < 8; jp++) {
                    unsigned b0, b1, b2, b3;
                    ldmx4(b0, b1, b2, b3, Bbase + swz(bc0 + jp * 2048));
                    mma_bf16(d[2 * jp],     a0, a1, a2, a3, b0, b1);
                    mma_bf16(d[2 * jp + 1], a0, a1, a2, a3, b2, b3);
                }
            }
        }
        __syncthreads();
    }

    // ---- epilogue: d[j][.]: rows (16w + g, +8), cols x0 + j*8 + (lane&3)*2
    const int g = lane >> 2, c2 = (lane & 3) * 2;
    const int cout0 = 16 * w + g;
    const float bias0 = bc[cout0], bias1 = bc[cout0 + 8];
    float* h0 = g_h + ((size_t)(b * CO + cout0) << 16) + y * WW + x0 + c2;
    float* h1 = h0 + ((size_t)8 << 16);
#pragma unroll
    for (int j = 0; j < 16; j++) {
        float2 v0 = make_float2(d[j][0] + bias0, d[j][1] + bias0);
        float2 v1 = make_float2(d[j][2] + bias1, d[j][3] + bias1);
        *reinterpret_cast<float2*>(h0 + j * 8) = v0;
        *reinterpret_cast<float2*>(h1 + j * 8) = v1;
    }
}

// ---------------------------------------------------------------------------
// Kernel 2 (FUSED mc + au): unchanged from R6 (907us best).
// ---------------------------------------------------------------------------
#define FILL_N 1360
#define FILL_SLOTS 6

__global__ __launch_bounds__(256, 2) void mcau_kernel(
    const float* __restrict__ lms, const float* __restrict__ Wo,
    const float* __restrict__ bo, const float* __restrict__ masks,
    const float* __restrict__ Wa, const float* __restrict__ ba,
    float* __restrict__ out)
{
    __shared__ float sWm[128 * 64];
    __shared__ float sWa[128 * 9 * 4];
    __shared__ float sX[2][4 * 10 * 36];

    const int tid = threadIdx.x;
    for (int i = tid; i < 128 * 64; i += 256) {
        int c = i >> 6, t = (i >> 2) & 15, o = i & 3;
        sWm[i] = Wo[o * 128 + c] * masks[t * 128 + c];
    }
    for (int i = tid; i < 128 * 36; i += 256) {
        int ci = i / 36, rem = i % 36, k = rem >> 2, o = rem & 3;
        sWa[i] = Wa[(o * 128 + ci) * 9 + k];
    }

    const int b  = blockIdx.z;
    const int y0 = blockIdx.y * 8;
    const int x0 = blockIdx.x * 32;
    const int row = tid >> 5;
    const int col = tid & 31;

    int smoff[FILL_SLOTS]; int goff[FILL_SLOTS]; int gok[FILL_SLOTS];
#pragma unroll
    for (int s = 0; s < FILL_SLOTS; s++) {
        int i = tid + s * 256;
        smoff[s] = -1; goff[s] = 0; gok[s] = 0;
        if (i < FILL_N) {
            int ci = i / 340, r = (i / 34) % 10, c = i % 34;
            int gy = y0 - 1 + r, gx = x0 - 1 + c;
            smoff[s] = (ci * 10 + r) * 36 + c;
            if (gy >= 0 && gy < HH && gx >= 0 && gx < WW) {
                gok[s] = 1;
                goff[s] = ((b * CO + ci) * HH + gy) * WW + gx;
            }
        }
    }

    unsigned sXb[2];
    sXb[0] = (unsigned)__cvta_generic_to_shared(&sX[0][0]);
    sXb[1] = (unsigned)__cvta_generic_to_shared(&sX[1][0]);

    auto prefetch = [&](int cc, int bf) {
        const float* hsrc = g_h + (size_t)cc * 4 * HWP;
#pragma unroll
        for (int s = 0; s < FILL_SLOTS; s++) {
            if (smoff[s] >= 0)
                cpa4z(sXb[bf] + smoff[s] * 4, hsrc + goff[s], gok[s]);
        }
        cpa_commit();
    };

    u64 mcA[16], mcB[16];
#pragma unroll
    for (int t = 0; t < 16; t++) { mcA[t] = 0ull; mcB[t] = 0ull; }
    u64 auA = 0ull, auB = 0ull;

    prefetch(0, 0);
    __syncthreads();

    for (int cc = 0; cc < 32; cc++) {
        const int bf = cc & 1;
        cpa_wait_all();
        __syncthreads();
        if (cc < 31) prefetch(cc + 1, bf ^ 1);

        const float* sXc = &sX[bf][0];
#pragma unroll
        for (int ci = 0; ci < 4; ci++) {
            float hv = sXc[(ci * 10 + row + 1) * 36 + col + 1];
            u64 hd = dup2(hv);
            const ulonglong2* wr =
                reinterpret_cast<const ulonglong2*>(&sWm[(cc * 4 + ci) * 64]);
#pragma unroll
            for (int t = 0; t < 16; t++) {
                ulonglong2 w = wr[t];
                fma2(mcA[t], w.x, hd);
                fma2(mcB[t], w.y, hd);
            }
#pragma unroll
            for (int ky = 0; ky < 3; ky++) {
                const float* xr = &sXc[(ci * 10 + row + ky) * 36 + col];
                float v0 = xr[0], v1 = xr[1], v2 = xr[2];
                const ulonglong2* wk = reinterpret_cast<const ulonglong2*>(
                    &sWa[((cc * 4 + ci) * 9 + ky * 3) * 4]);
                ulonglong2 w0 = wk[0], w1 = wk[1], w2 = wk[2];
                u64 x0d = dup2(v0), x1d = dup2(v1), x2d = dup2(v2);
                fma2(auA, w0.x, x0d); fma2(auB, w0.y, x0d);
                fma2(auA, w1.x, x1d); fma2(auB, w1.y, x1d);
                fma2(auA, w2.x, x2d); fma2(auB, w2.y, x2d);
            }
        }
        __syncthreads();
    }

    const int pix = (y0 + row) * WW + x0 + col;

    float a[16][4];
#pragma unroll
    for (int t = 0; t < 16; t++) {
        float2 f01 = unpk(mcA[t]);
        float2 f23 = unpk(mcB[t]);
        a[t][0] = f01.x; a[t][1] = f01.y; a[t][2] = f23.x; a[t][3] = f23.y;
    }
#pragma unroll
    for (int o = 0; o < 4; o++) {
        float bb = bo[o];
        float s[16];
        float sum = 0.f;
#pragma unroll
        for (int t = 0; t < 16; t++) {
            float v = fast_tanh(a[t][o] + bb);
            s[t] = v;
            sum += v;
        }
        float mn = sum * 0.0625f;
        float var = 0.f;
#pragma unroll
        for (int t = 0; t < 16; t++) {
            float dd = s[t] - mn;
            var += dd * dd;
        }
        var *= (1.f / 15.f);
        int oidx = (b * 4 + o) * HWP + pix;
        out[NOUT + oidx]     = var;
        out[2 * NOUT + oidx] = mn + lms[oidx];
    }

    {
        float2 f01 = unpk(auA);
        float2 f23 = unpk(auB);
        float av[4] = { f01.x, f01.y, f23.x, f23.y };
#pragma unroll
        for (int o = 0; o < 4; o++)
            out[(b * 4 + o) * HWP + pix] = fast_sigmoid(av[o] + ba[o]);
    }
}

// ---------------------------------------------------------------------------
extern "C" void kernel_launch(void* const* d_in, const int* in_sizes, int n_in,
                              void* d_out, int out_size) {
    const float* x     = (const float*)d_in[0];
    const float* lms   = (const float*)d_in[1];
    const float* Wc    = (const float*)d_in[2];
    const float* bc    = (const float*)d_in[3];
    const float* Wo    = (const float*)d_in[4];
    const float* bo    = (const float*)d_in[5];
    const float* Wa    = (const float*)d_in[6];
    const float* ba    = (const float*)d_in[7];
    const float* masks = (const float*)d_in[8];
    float* out = (float*)d_out;

    cudaFuncSetAttribute(conv_hmma,
                         cudaFuncAttributeMaxDynamicSharedMemorySize, CV_SMEM);

    wprep<<<288, 256>>>(Wc);
    xprep<<<8192, 256>>>(x);
    conv_hmma<<<2048, 256, CV_SMEM>>>(bc);
    mcau_kernel<<<dim3(8, 32, 4), 256>>>(lms, Wo, bo, masks, Wa, ba, out);
}